// round 2
// baseline (speedup 1.0000x reference)
#include <cuda_runtime.h>
#include <math.h>

// ---------------- problem constants ----------------
#define BATCHN 8
#define SEQLEN 4097
#define LMAIN  4096
#define DMODEL 384
#define DINNER 768
#define DHALF  384
#define DSTATE 16
#define DTRANK 24
#define MROWS  (BATCHN * SEQLEN)        // 32776
#define XDBLW  (DTRANK + 2 * DSTATE)    // 56

#define CHUNK  64
#define NCH    ((SEQLEN + CHUNK - 1) / CHUNK)  // 65

// ---------------- scratch (device globals; no allocation allowed) ----------------
__device__ float g_xz   [(size_t)MROWS * DINNER];   // (B,L,768) permuted order
__device__ float g_x    [(size_t)MROWS * DHALF];    // conv+silu x
__device__ float g_z    [(size_t)MROWS * DHALF];    // conv+silu z
__device__ float g_xdbl [(size_t)MROWS * XDBLW];    // [dt_low(24) | B(16) | C(16)]
__device__ float g_dt   [(size_t)MROWS * DHALF];    // softplus(dt + bias)
__device__ float g_yz   [(size_t)MROWS * DHALF];    // (y + D*x) * z
__device__ float g_hout [(size_t)BATCHN * NCH * DHALF * DSTATE];
__device__ float g_hin  [(size_t)BATCHN * NCH * DHALF * DSTATE];
__device__ float g_dtsum[(size_t)BATCHN * NCH * DHALF];
__device__ int   g_perm [LMAIN];                    // canonical int32 permutation

// ---------------- perm canonicalization ----------------
// The reference builds perm with .astype(jnp.int64); under default JAX config
// that is silently int32. Detect on-device: viewing the buffer as int32 words,
// an int64-LE layout has ALL odd words == 0 (values < 4096); an int32
// permutation of 0..4095 cannot (distinct values, at most one zero).
__global__ void __launch_bounds__(1024) perm_canon_kernel(const int* __restrict__ praw)
{
    __shared__ int odd_nonzero;
    if (threadIdx.x == 0) odd_nonzero = 0;
    __syncthreads();
    int local = 0;
    for (int i = threadIdx.x; i < LMAIN / 2; i += 1024)
        if (praw[2 * i + 1] != 0) local = 1;
    if (local) atomicOr(&odd_nonzero, 1);
    __syncthreads();
    bool is64 = (odd_nonzero == 0);
    for (int i = threadIdx.x; i < LMAIN; i += 1024)
        g_perm[i] = is64 ? praw[2 * i] : praw[i];
}

// ---------------- helpers ----------------
__device__ __forceinline__ int perm_row(int m, const int* __restrict__ p) {
    if (p == nullptr) return m;
    int lp = m % SEQLEN;
    if (lp == 0) return m;
    return m - lp + 1 + p[lp - 1];
}

__device__ __forceinline__ float softplusf(float v) {
    return (v > 20.0f) ? v : log1pf(__expf(v));
}

__device__ __forceinline__ float siluf(float v) {
    return v / (1.0f + __expf(-v));
}

// ---------------- tiled NT GEMM: C[M,N] = A[M,K] * B[N,K]^T ----------------
// BM=128, BN=64, BK=16, 256 threads, 8x4 per-thread microtile.
// Optional row gather on A / row scatter on C via the permutation.
// EPI=1: softplus(acc + bias[n]).
#define GBM 128
#define GBN 64
#define GBK 16

template <int EPI>
__global__ void __launch_bounds__(256) gemm_nt(
    const float* __restrict__ A, const float* __restrict__ Bw,
    float* __restrict__ C,
    int M, int N, int K, int lda, int ldb, int ldc,
    const int* __restrict__ gperm,
    const int* __restrict__ sperm,
    const float* __restrict__ bias)
{
    __shared__ float As[GBK][GBM];
    __shared__ float Bs[GBK][GBN];

    const int t   = threadIdx.x;
    const int bn0 = blockIdx.x * GBN;
    const int bm0 = blockIdx.y * GBM;
    const int tx  = t & 15;   // n dim
    const int ty  = t >> 4;   // m dim

    float acc[8][4];
#pragma unroll
    for (int i = 0; i < 8; i++)
#pragma unroll
        for (int j = 0; j < 4; j++) acc[i][j] = 0.0f;

    for (int k0 = 0; k0 < K; k0 += GBK) {
        // stage A: 128 rows x 16 k  (2 float4 per thread)
#pragma unroll
        for (int i = 0; i < 2; i++) {
            int id = t + i * 256;
            int r  = id >> 2;
            int kq = id & 3;
            int m  = bm0 + r;
            float4 v = make_float4(0.f, 0.f, 0.f, 0.f);
            if (m < M && (k0 + kq * 4) < K) {
                int src = perm_row(m, gperm);
                v = *(const float4*)(A + (size_t)src * lda + k0 + kq * 4);
            }
            As[kq * 4 + 0][r] = v.x;
            As[kq * 4 + 1][r] = v.y;
            As[kq * 4 + 2][r] = v.z;
            As[kq * 4 + 3][r] = v.w;
        }
        // stage B: 64 rows x 16 k  (1 float4 per thread)
        {
            int r  = t >> 2;
            int kq = t & 3;
            int n  = bn0 + r;
            float4 v = make_float4(0.f, 0.f, 0.f, 0.f);
            if (n < N && (k0 + kq * 4) < K)
                v = *(const float4*)(Bw + (size_t)n * ldb + k0 + kq * 4);
            Bs[kq * 4 + 0][r] = v.x;
            Bs[kq * 4 + 1][r] = v.y;
            Bs[kq * 4 + 2][r] = v.z;
            Bs[kq * 4 + 3][r] = v.w;
        }
        __syncthreads();

#pragma unroll
        for (int kk = 0; kk < GBK; kk++) {
            float4 a0 = *(const float4*)&As[kk][ty * 8];
            float4 a1 = *(const float4*)&As[kk][ty * 8 + 4];
            float4 b0 = *(const float4*)&Bs[kk][tx * 4];
            float av[8] = {a0.x, a0.y, a0.z, a0.w, a1.x, a1.y, a1.z, a1.w};
            float bv[4] = {b0.x, b0.y, b0.z, b0.w};
#pragma unroll
            for (int i = 0; i < 8; i++)
#pragma unroll
                for (int j = 0; j < 4; j++) acc[i][j] += av[i] * bv[j];
        }
        __syncthreads();
    }

#pragma unroll
    for (int i = 0; i < 8; i++) {
        int m = bm0 + ty * 8 + i;
        if (m >= M) continue;
        int dst = perm_row(m, sperm);
#pragma unroll
        for (int j = 0; j < 4; j++) {
            int n = bn0 + tx * 4 + j;
            if (n >= N) continue;
            float v = acc[i][j];
            if (EPI == 1) v = softplusf(v + bias[n]);
            C[(size_t)dst * ldc + n] = v;
        }
    }
}

// ---------------- depthwise conv (k=4, pad 1 left / 2 right) + SiLU ----------------
__global__ void conv_silu_kernel(const float* __restrict__ xz,
                                 const float* __restrict__ wx,
                                 const float* __restrict__ wz,
                                 float* __restrict__ xo,
                                 float* __restrict__ zo)
{
    int idx = blockIdx.x * blockDim.x + threadIdx.x;
    if (idx >= MROWS * DHALF) return;
    int c = idx % DHALF;
    int m = idx / DHALF;
    int l = m % SEQLEN;
    int b = m / SEQLEN;

    float ax = 0.f, az = 0.f;
#pragma unroll
    for (int k = 0; k < 4; k++) {
        int ll = l - 1 + k;
        if (ll >= 0 && ll < SEQLEN) {
            const float* p = xz + ((size_t)(b * SEQLEN + ll)) * DINNER;
            ax += wx[c * 4 + k] * p[c];
            az += wz[c * 4 + k] * p[DHALF + c];
        }
    }
    xo[idx] = siluf(ax);
    zo[idx] = siluf(az);
}

// ---------------- scan pass 1: per-chunk h_out and sum(dt) ----------------
__global__ void __launch_bounds__(128) scan_pass1(const float* __restrict__ A_log)
{
    int bid = blockIdx.x;
    int dg  = bid % 3;
    int c   = (bid / 3) % NCH;
    int b   = bid / (3 * NCH);
    int d   = dg * 128 + threadIdx.x;

    float Aa[DSTATE];
#pragma unroll
    for (int n = 0; n < DSTATE; n++) Aa[n] = -__expf(A_log[d * DSTATE + n]);

    float h[DSTATE];
#pragma unroll
    for (int n = 0; n < DSTATE; n++) h[n] = 0.0f;
    float dts = 0.0f;

    int t0 = c * CHUNK;
    int t1 = min(SEQLEN, t0 + CHUNK);
    for (int t = t0; t < t1; t++) {
        size_t m  = (size_t)b * SEQLEN + t;
        float dtv = g_dt[m * DHALF + d];
        float xv  = g_x[m * DHALF + d];
        dts += dtv;
        const float4* Bp = (const float4*)(g_xdbl + m * XDBLW + DTRANK);
        float4 B0 = Bp[0], B1 = Bp[1], B2 = Bp[2], B3 = Bp[3];
        float Bv[DSTATE] = {B0.x, B0.y, B0.z, B0.w, B1.x, B1.y, B1.z, B1.w,
                            B2.x, B2.y, B2.z, B2.w, B3.x, B3.y, B3.z, B3.w};
        float dtx = dtv * xv;
#pragma unroll
        for (int n = 0; n < DSTATE; n++) {
            float a = __expf(dtv * Aa[n]);
            h[n] = h[n] * a + dtx * Bv[n];
        }
    }

    size_t base = ((size_t)b * NCH + c) * DHALF + d;
    float4* ho = (float4*)(g_hout + base * DSTATE);
    ho[0] = make_float4(h[0], h[1], h[2], h[3]);
    ho[1] = make_float4(h[4], h[5], h[6], h[7]);
    ho[2] = make_float4(h[8], h[9], h[10], h[11]);
    ho[3] = make_float4(h[12], h[13], h[14], h[15]);
    g_dtsum[base] = dts;
}

// ---------------- scan pass 2: serial combine across chunks ----------------
__global__ void scan_pass2(const float* __restrict__ A_log)
{
    int idx = blockIdx.x * blockDim.x + threadIdx.x;
    if (idx >= BATCHN * DHALF * DSTATE) return;
    int n = idx & 15;
    int d = (idx >> 4) % DHALF;
    int b = idx / (DSTATE * DHALF);

    float Aa = -__expf(A_log[d * DSTATE + n]);
    float h = 0.0f;
    for (int c = 0; c < NCH; c++) {
        size_t base = ((size_t)b * NCH + c) * DHALF + d;
        g_hin[base * DSTATE + n] = h;
        float a = __expf(Aa * g_dtsum[base]);
        h = h * a + g_hout[base * DSTATE + n];
    }
}

// ---------------- scan pass 3: replay with h_in, fuse y, D*x, z gate ----------------
__global__ void __launch_bounds__(128) scan_pass3(const float* __restrict__ A_log,
                                                  const float* __restrict__ D_param)
{
    int bid = blockIdx.x;
    int dg  = bid % 3;
    int c   = (bid / 3) % NCH;
    int b   = bid / (3 * NCH);
    int d   = dg * 128 + threadIdx.x;

    float Aa[DSTATE];
#pragma unroll
    for (int n = 0; n < DSTATE; n++) Aa[n] = -__expf(A_log[d * DSTATE + n]);
    float Dv = D_param[d];

    size_t sbase = ((size_t)b * NCH + c) * DHALF + d;
    const float4* hi = (const float4*)(g_hin + sbase * DSTATE);
    float4 h0 = hi[0], h1 = hi[1], h2 = hi[2], h3 = hi[3];
    float h[DSTATE] = {h0.x, h0.y, h0.z, h0.w, h1.x, h1.y, h1.z, h1.w,
                       h2.x, h2.y, h2.z, h2.w, h3.x, h3.y, h3.z, h3.w};

    int t0 = c * CHUNK;
    int t1 = min(SEQLEN, t0 + CHUNK);
    for (int t = t0; t < t1; t++) {
        size_t m  = (size_t)b * SEQLEN + t;
        float dtv = g_dt[m * DHALF + d];
        float xv  = g_x[m * DHALF + d];
        const float4* Bp = (const float4*)(g_xdbl + m * XDBLW + DTRANK);
        float4 B0 = Bp[0], B1 = Bp[1], B2 = Bp[2], B3 = Bp[3];
        const float4* Cp = (const float4*)(g_xdbl + m * XDBLW + DTRANK + DSTATE);
        float4 C0 = Cp[0], C1 = Cp[1], C2 = Cp[2], C3 = Cp[3];
        float Bv[DSTATE] = {B0.x, B0.y, B0.z, B0.w, B1.x, B1.y, B1.z, B1.w,
                            B2.x, B2.y, B2.z, B2.w, B3.x, B3.y, B3.z, B3.w};
        float Cv[DSTATE] = {C0.x, C0.y, C0.z, C0.w, C1.x, C1.y, C1.z, C1.w,
                            C2.x, C2.y, C2.z, C2.w, C3.x, C3.y, C3.z, C3.w};
        float dtx = dtv * xv;
        float y = 0.0f;
#pragma unroll
        for (int n = 0; n < DSTATE; n++) {
            float a = __expf(dtv * Aa[n]);
            h[n] = h[n] * a + dtx * Bv[n];
            y += h[n] * Cv[n];
        }
        float zv = g_z[m * DHALF + d];
        g_yz[m * DHALF + d] = (y + Dv * xv) * zv;
    }
}

// ---------------- launch ----------------
extern "C" void kernel_launch(void* const* d_in, const int* in_sizes, int n_in,
                              void* d_out, int out_size)
{
    const float* hidden     = (const float*)d_in[0];
    const float* in_proj_w  = (const float*)d_in[1];
    const float* conv_x_w   = (const float*)d_in[2];
    const float* conv_z_w   = (const float*)d_in[3];
    const float* x_proj_w   = (const float*)d_in[4];
    const float* dt_proj_w  = (const float*)d_in[5];
    const float* dt_proj_b  = (const float*)d_in[6];
    const float* A_log      = (const float*)d_in[7];
    const float* D_param    = (const float*)d_in[8];
    const float* out_proj_w = (const float*)d_in[9];
    const int*   perm_raw   = (const int*)d_in[10];
    float* out = (float*)d_out;

    float *p_xz, *p_x, *p_z, *p_xdbl, *p_dt, *p_yz;
    int   *p_perm;
    cudaGetSymbolAddress((void**)&p_xz,   g_xz);
    cudaGetSymbolAddress((void**)&p_x,    g_x);
    cudaGetSymbolAddress((void**)&p_z,    g_z);
    cudaGetSymbolAddress((void**)&p_xdbl, g_xdbl);
    cudaGetSymbolAddress((void**)&p_dt,   g_dt);
    cudaGetSymbolAddress((void**)&p_yz,   g_yz);
    cudaGetSymbolAddress((void**)&p_perm, g_perm);

    const int mblocks = (MROWS + GBM - 1) / GBM;  // 257

    // 0) canonicalize perm (handles int32 or int64 storage)
    perm_canon_kernel<<<1, 1024>>>(perm_raw);

    // 1) in_proj with gather-permute: xz[m,e] = hidden[src(m),:] . W[e,:]
    gemm_nt<0><<<dim3(DINNER / GBN, mblocks), 256>>>(
        hidden, in_proj_w, p_xz, MROWS, DINNER, DMODEL,
        DMODEL, DMODEL, DINNER, p_perm, nullptr, nullptr);

    // 2) depthwise conv + silu for x and z halves
    conv_silu_kernel<<<(MROWS * DHALF + 255) / 256, 256>>>(
        p_xz, conv_x_w, conv_z_w, p_x, p_z);

    // 3) x_proj: x_dbl[m, 0..55]
    gemm_nt<0><<<dim3(1, mblocks), 256>>>(
        p_x, x_proj_w, p_xdbl, MROWS, XDBLW, DHALF,
        DHALF, DHALF, XDBLW, nullptr, nullptr, nullptr);

    // 4) dt projection + softplus(.+bias)
    gemm_nt<1><<<dim3(DHALF / GBN, mblocks), 256>>>(
        p_xdbl, dt_proj_w, p_dt, MROWS, DHALF, DTRANK,
        XDBLW, DTRANK, DHALF, nullptr, nullptr, dt_proj_b);

    // 5) chunked selective scan
    scan_pass1<<<BATCHN * NCH * 3, 128>>>(A_log);
    scan_pass2<<<(BATCHN * DHALF * DSTATE + 255) / 256, 256>>>(A_log);
    scan_pass3<<<BATCHN * NCH * 3, 128>>>(A_log, D_param);

    // 6) out_proj with scatter (undo permutation)
    gemm_nt<0><<<dim3(DMODEL / GBN, mblocks), 256>>>(
        p_yz, out_proj_w, out, MROWS, DMODEL, DHALF,
        DHALF, DHALF, DMODEL, nullptr, p_perm, nullptr);
}

// round 3
// speedup vs baseline: 1.1369x; 1.1369x over previous
#include <cuda_runtime.h>
#include <mma.h>
#include <math.h>

using namespace nvcuda;

// ---------------- problem constants ----------------
#define BATCHN 8
#define SEQLEN 4097
#define LMAIN  4096
#define DMODEL 384
#define DINNER 768
#define DHALF  384
#define DSTATE 16
#define DTRANK 24
#define MROWS  (BATCHN * SEQLEN)        // 32776
#define XDBLW  (DTRANK + 2 * DSTATE)    // 56

#define CHUNK  64
#define NCH    ((SEQLEN + CHUNK - 1) / CHUNK)  // 65

// ---------------- scratch (device globals; no allocation allowed) ----------------
__device__ float g_xz   [(size_t)MROWS * DINNER];
__device__ float g_x    [(size_t)MROWS * DHALF];
__device__ float g_z    [(size_t)MROWS * DHALF];
__device__ float g_xdbl [(size_t)MROWS * XDBLW];
__device__ float g_dt   [(size_t)MROWS * DHALF];
__device__ float g_yz   [(size_t)MROWS * DHALF];
__device__ float g_hout [(size_t)BATCHN * NCH * DHALF * DSTATE];
__device__ float g_hin  [(size_t)BATCHN * NCH * DHALF * DSTATE];
__device__ float g_dtsum[(size_t)BATCHN * NCH * DHALF];
__device__ int   g_perm [LMAIN];
__device__ int   g_afast;    // 1 if A[d,n] == -(n+1) structure holds

// ---------------- prep: perm canonicalization + A-structure detection ----------------
__global__ void __launch_bounds__(1024) prep_kernel(const int* __restrict__ praw,
                                                    const float* __restrict__ A_log)
{
    __shared__ int odd_nonzero;
    __shared__ int a_bad;
    if (threadIdx.x == 0) { odd_nonzero = 0; a_bad = 0; }
    __syncthreads();
    int local = 0;
    for (int i = threadIdx.x; i < LMAIN / 2; i += 1024)
        if (praw[2 * i + 1] != 0) local = 1;
    if (local) atomicOr(&odd_nonzero, 1);

    int bad = 0;
    for (int i = threadIdx.x; i < DHALF * DSTATE; i += 1024) {
        int n = i & 15;
        float ref = logf((float)(n + 1));
        if (fabsf(A_log[i] - ref) > 1e-5f) bad = 1;
    }
    if (bad) atomicOr(&a_bad, 1);
    __syncthreads();
    bool is64 = (odd_nonzero == 0);
    for (int i = threadIdx.x; i < LMAIN; i += 1024)
        g_perm[i] = is64 ? praw[2 * i] : praw[i];
    if (threadIdx.x == 0) g_afast = (a_bad == 0) ? 1 : 0;
}

// ---------------- helpers ----------------
__device__ __forceinline__ int perm_row(int m, const int* __restrict__ p) {
    if (p == nullptr) return m;
    int lp = m % SEQLEN;
    if (lp == 0) return m;
    return m - lp + 1 + p[lp - 1];
}

__device__ __forceinline__ float softplusf(float v) {
    return (v > 20.0f) ? v : log1pf(__expf(v));
}

__device__ __forceinline__ float siluf(float v) {
    return v / (1.0f + __expf(-v));
}

__device__ __forceinline__ float to_tf32(float x) {
    unsigned u;
    asm("cvt.rna.tf32.f32 %0, %1;" : "=r"(u) : "f"(x));
    return __uint_as_float(u);
}

// ---------------- WMMA tf32 NT GEMM: C[M,N] = A[M,K] * B[N,K]^T ----------------
// BM=128, BN=64, BK=32, 256 threads (8 warps, 4x2), warp tile 32x32.
// K must be a multiple of 32, N a multiple of 64. Optional gather on A rows,
// scatter on C rows.
#define WBM 128
#define WBN 64
#define WBK 32
#define WLD (WBK + 4)   // 36, multiple of 4

__global__ void __launch_bounds__(256) gemm_wmma(
    const float* __restrict__ A, const float* __restrict__ Bw,
    float* __restrict__ C,
    int M, int N, int K, int lda, int ldb, int ldc,
    const int* __restrict__ gperm,
    const int* __restrict__ sperm)
{
    __shared__ float sbuf[WBM * 68];          // max(As+Bs = 6912, Cs = 8704) floats
    float* As = sbuf;                          // [WBM][WLD]
    float* Bs = sbuf + WBM * WLD;              // [WBN][WLD]
    float* Cs = sbuf;                          // [WBM][68] (aliases after mainloop)

    const int t    = threadIdx.x;
    const int warp = t >> 5;
    const int wm   = warp & 3;                 // 0..3 (m)
    const int wn   = warp >> 2;                // 0..1 (n)
    const int bn0  = blockIdx.x * WBN;
    const int bm0  = blockIdx.y * WBM;

    wmma::fragment<wmma::accumulator, 16, 16, 8, float> fc[2][2];
#pragma unroll
    for (int i = 0; i < 2; i++)
#pragma unroll
        for (int j = 0; j < 2; j++) wmma::fill_fragment(fc[i][j], 0.0f);

    for (int k0 = 0; k0 < K; k0 += WBK) {
        // stage A: 128 rows x 32 k = 1024 float4, 4 per thread
#pragma unroll
        for (int i = 0; i < 4; i++) {
            int f  = t + i * 256;
            int r  = f >> 3;
            int c4 = f & 7;
            int m  = bm0 + r;
            float4 v = make_float4(0.f, 0.f, 0.f, 0.f);
            if (m < M) {
                int src = perm_row(m, gperm);
                v = *(const float4*)(A + (size_t)src * lda + k0 + c4 * 4);
            }
            float* dst = As + r * WLD + c4 * 4;
            dst[0] = to_tf32(v.x); dst[1] = to_tf32(v.y);
            dst[2] = to_tf32(v.z); dst[3] = to_tf32(v.w);
        }
        // stage B: 64 rows x 32 k = 512 float4, 2 per thread
#pragma unroll
        for (int i = 0; i < 2; i++) {
            int f  = t + i * 256;
            int r  = f >> 3;
            int c4 = f & 7;
            int n  = bn0 + r;
            float4 v = make_float4(0.f, 0.f, 0.f, 0.f);
            if (n < N)
                v = *(const float4*)(Bw + (size_t)n * ldb + k0 + c4 * 4);
            float* dst = Bs + r * WLD + c4 * 4;
            dst[0] = to_tf32(v.x); dst[1] = to_tf32(v.y);
            dst[2] = to_tf32(v.z); dst[3] = to_tf32(v.w);
        }
        __syncthreads();

#pragma unroll
        for (int ks = 0; ks < WBK; ks += 8) {
            wmma::fragment<wmma::matrix_a, 16, 16, 8, wmma::precision::tf32, wmma::row_major> fa[2];
            wmma::fragment<wmma::matrix_b, 16, 16, 8, wmma::precision::tf32, wmma::col_major> fb[2];
#pragma unroll
            for (int i = 0; i < 2; i++)
                wmma::load_matrix_sync(fa[i], As + (wm * 32 + i * 16) * WLD + ks, WLD);
#pragma unroll
            for (int j = 0; j < 2; j++)
                wmma::load_matrix_sync(fb[j], Bs + (wn * 32 + j * 16) * WLD + ks, WLD);
#pragma unroll
            for (int i = 0; i < 2; i++)
#pragma unroll
                for (int j = 0; j < 2; j++)
                    wmma::mma_sync(fc[i][j], fa[i], fb[j], fc[i][j]);
        }
        __syncthreads();
    }

    // epilogue: stage to smem, then permuted row copy to global
#pragma unroll
    for (int i = 0; i < 2; i++)
#pragma unroll
        for (int j = 0; j < 2; j++)
            wmma::store_matrix_sync(Cs + (wm * 32 + i * 16) * 68 + wn * 32 + j * 16,
                                    fc[i][j], 68, wmma::mem_row_major);
    __syncthreads();

#pragma unroll
    for (int i = 0; i < 8; i++) {
        int f  = t + i * 256;
        int r  = f >> 4;
        int c4 = f & 15;
        int m  = bm0 + r;
        if (m >= M) continue;
        int dst = perm_row(m, sperm);
        int n   = bn0 + c4 * 4;
        const float* src = Cs + r * 68 + c4 * 4;
        *(float4*)(C + (size_t)dst * ldc + n) =
            make_float4(src[0], src[1], src[2], src[3]);
    }
}

// ---------------- SIMT NT GEMM (small GEMMs): C[M,N] = A[M,K] * B[N,K]^T ----------------
#define GBM 128
#define GBN 64
#define GBK 16

template <int EPI>
__global__ void __launch_bounds__(256) gemm_nt(
    const float* __restrict__ A, const float* __restrict__ Bw,
    float* __restrict__ C,
    int M, int N, int K, int lda, int ldb, int ldc,
    const int* __restrict__ gperm,
    const int* __restrict__ sperm,
    const float* __restrict__ bias)
{
    __shared__ float As[GBK][GBM];
    __shared__ float Bs[GBK][GBN];

    const int t   = threadIdx.x;
    const int bn0 = blockIdx.x * GBN;
    const int bm0 = blockIdx.y * GBM;
    const int tx  = t & 15;
    const int ty  = t >> 4;

    float acc[8][4];
#pragma unroll
    for (int i = 0; i < 8; i++)
#pragma unroll
        for (int j = 0; j < 4; j++) acc[i][j] = 0.0f;

    for (int k0 = 0; k0 < K; k0 += GBK) {
#pragma unroll
        for (int i = 0; i < 2; i++) {
            int id = t + i * 256;
            int r  = id >> 2;
            int kq = id & 3;
            int m  = bm0 + r;
            float4 v = make_float4(0.f, 0.f, 0.f, 0.f);
            if (m < M && (k0 + kq * 4) < K) {
                int src = perm_row(m, gperm);
                v = *(const float4*)(A + (size_t)src * lda + k0 + kq * 4);
            }
            As[kq * 4 + 0][r] = v.x;
            As[kq * 4 + 1][r] = v.y;
            As[kq * 4 + 2][r] = v.z;
            As[kq * 4 + 3][r] = v.w;
        }
        {
            int r  = t >> 2;
            int kq = t & 3;
            int n  = bn0 + r;
            float4 v = make_float4(0.f, 0.f, 0.f, 0.f);
            if (n < N && (k0 + kq * 4) < K)
                v = *(const float4*)(Bw + (size_t)n * ldb + k0 + kq * 4);
            Bs[kq * 4 + 0][r] = v.x;
            Bs[kq * 4 + 1][r] = v.y;
            Bs[kq * 4 + 2][r] = v.z;
            Bs[kq * 4 + 3][r] = v.w;
        }
        __syncthreads();

#pragma unroll
        for (int kk = 0; kk < GBK; kk++) {
            float4 a0 = *(const float4*)&As[kk][ty * 8];
            float4 a1 = *(const float4*)&As[kk][ty * 8 + 4];
            float4 b0 = *(const float4*)&Bs[kk][tx * 4];
            float av[8] = {a0.x, a0.y, a0.z, a0.w, a1.x, a1.y, a1.z, a1.w};
            float bv[4] = {b0.x, b0.y, b0.z, b0.w};
#pragma unroll
            for (int i = 0; i < 8; i++)
#pragma unroll
                for (int j = 0; j < 4; j++) acc[i][j] += av[i] * bv[j];
        }
        __syncthreads();
    }

#pragma unroll
    for (int i = 0; i < 8; i++) {
        int m = bm0 + ty * 8 + i;
        if (m >= M) continue;
        int dst = perm_row(m, sperm);
#pragma unroll
        for (int j = 0; j < 4; j++) {
            int n = bn0 + tx * 4 + j;
            if (n >= N) continue;
            float v = acc[i][j];
            if (EPI == 1) v = softplusf(v + bias[n]);
            C[(size_t)dst * ldc + n] = v;
        }
    }
}

// ---------------- depthwise conv (k=4, pad 1 left / 2 right) + SiLU ----------------
__global__ void conv_silu_kernel(const float* __restrict__ xz,
                                 const float* __restrict__ wx,
                                 const float* __restrict__ wz,
                                 float* __restrict__ xo,
                                 float* __restrict__ zo)
{
    int idx = blockIdx.x * blockDim.x + threadIdx.x;
    if (idx >= MROWS * DHALF) return;
    int c = idx % DHALF;
    int m = idx / DHALF;
    int l = m % SEQLEN;
    int b = m / SEQLEN;

    float ax = 0.f, az = 0.f;
#pragma unroll
    for (int k = 0; k < 4; k++) {
        int ll = l - 1 + k;
        if (ll >= 0 && ll < SEQLEN) {
            const float* p = xz + ((size_t)(b * SEQLEN + ll)) * DINNER;
            ax += wx[c * 4 + k] * p[c];
            az += wz[c * 4 + k] * p[DHALF + c];
        }
    }
    xo[idx] = siluf(ax);
    zo[idx] = siluf(az);
}

// ---------------- scan pass 1: per-chunk h_out and sum(dt) ----------------
__global__ void __launch_bounds__(128) scan_pass1(const float* __restrict__ A_log)
{
    int bid = blockIdx.x;
    int dg  = bid % 3;
    int c   = (bid / 3) % NCH;
    int b   = bid / (3 * NCH);
    int d   = dg * 128 + threadIdx.x;
    const bool afast = (g_afast != 0);

    float Aa[DSTATE];
#pragma unroll
    for (int n = 0; n < DSTATE; n++) Aa[n] = -__expf(A_log[d * DSTATE + n]);

    float h[DSTATE];
#pragma unroll
    for (int n = 0; n < DSTATE; n++) h[n] = 0.0f;
    float dts = 0.0f;

    int t0 = c * CHUNK;
    int t1 = min(SEQLEN, t0 + CHUNK);
    for (int t = t0; t < t1; t++) {
        size_t m  = (size_t)b * SEQLEN + t;
        float dtv = g_dt[m * DHALF + d];
        float xv  = g_x[m * DHALF + d];
        dts += dtv;
        const float4* Bp = (const float4*)(g_xdbl + m * XDBLW + DTRANK);
        float4 B0 = Bp[0], B1 = Bp[1], B2 = Bp[2], B3 = Bp[3];
        float Bv[DSTATE] = {B0.x, B0.y, B0.z, B0.w, B1.x, B1.y, B1.z, B1.w,
                            B2.x, B2.y, B2.z, B2.w, B3.x, B3.y, B3.z, B3.w};
        float dtx = dtv * xv;
        if (afast) {
            float e1 = __expf(-dtv);
            float a = 1.0f;
#pragma unroll
            for (int n = 0; n < DSTATE; n++) {
                a *= e1;                       // a = exp(-dt*(n+1))
                h[n] = h[n] * a + dtx * Bv[n];
            }
        } else {
#pragma unroll
            for (int n = 0; n < DSTATE; n++) {
                float a = __expf(dtv * Aa[n]);
                h[n] = h[n] * a + dtx * Bv[n];
            }
        }
    }

    size_t base = ((size_t)b * NCH + c) * DHALF + d;
    float4* ho = (float4*)(g_hout + base * DSTATE);
    ho[0] = make_float4(h[0], h[1], h[2], h[3]);
    ho[1] = make_float4(h[4], h[5], h[6], h[7]);
    ho[2] = make_float4(h[8], h[9], h[10], h[11]);
    ho[3] = make_float4(h[12], h[13], h[14], h[15]);
    g_dtsum[base] = dts;
}

// ---------------- scan pass 2: serial combine across chunks ----------------
__global__ void scan_pass2(const float* __restrict__ A_log)
{
    int idx = blockIdx.x * blockDim.x + threadIdx.x;
    if (idx >= BATCHN * DHALF * DSTATE) return;
    int n = idx & 15;
    int d = (idx >> 4) % DHALF;
    int b = idx / (DSTATE * DHALF);

    float Aa = -__expf(A_log[d * DSTATE + n]);
    float h = 0.0f;
    for (int c = 0; c < NCH; c++) {
        size_t base = ((size_t)b * NCH + c) * DHALF + d;
        g_hin[base * DSTATE + n] = h;
        float a = __expf(Aa * g_dtsum[base]);
        h = h * a + g_hout[base * DSTATE + n];
    }
}

// ---------------- scan pass 3: replay with h_in, fuse y, D*x, z gate ----------------
__global__ void __launch_bounds__(128) scan_pass3(const float* __restrict__ A_log,
                                                  const float* __restrict__ D_param)
{
    int bid = blockIdx.x;
    int dg  = bid % 3;
    int c   = (bid / 3) % NCH;
    int b   = bid / (3 * NCH);
    int d   = dg * 128 + threadIdx.x;
    const bool afast = (g_afast != 0);

    float Aa[DSTATE];
#pragma unroll
    for (int n = 0; n < DSTATE; n++) Aa[n] = -__expf(A_log[d * DSTATE + n]);
    float Dv = D_param[d];

    size_t sbase = ((size_t)b * NCH + c) * DHALF + d;
    const float4* hi = (const float4*)(g_hin + sbase * DSTATE);
    float4 h0 = hi[0], h1 = hi[1], h2 = hi[2], h3 = hi[3];
    float h[DSTATE] = {h0.x, h0.y, h0.z, h0.w, h1.x, h1.y, h1.z, h1.w,
                       h2.x, h2.y, h2.z, h2.w, h3.x, h3.y, h3.z, h3.w};

    int t0 = c * CHUNK;
    int t1 = min(SEQLEN, t0 + CHUNK);
    for (int t = t0; t < t1; t++) {
        size_t m  = (size_t)b * SEQLEN + t;
        float dtv = g_dt[m * DHALF + d];
        float xv  = g_x[m * DHALF + d];
        const float4* Bp = (const float4*)(g_xdbl + m * XDBLW + DTRANK);
        float4 B0 = Bp[0], B1 = Bp[1], B2 = Bp[2], B3 = Bp[3];
        const float4* Cp = (const float4*)(g_xdbl + m * XDBLW + DTRANK + DSTATE);
        float4 C0 = Cp[0], C1 = Cp[1], C2 = Cp[2], C3 = Cp[3];
        float Bv[DSTATE] = {B0.x, B0.y, B0.z, B0.w, B1.x, B1.y, B1.z, B1.w,
                            B2.x, B2.y, B2.z, B2.w, B3.x, B3.y, B3.z, B3.w};
        float Cv[DSTATE] = {C0.x, C0.y, C0.z, C0.w, C1.x, C1.y, C1.z, C1.w,
                            C2.x, C2.y, C2.z, C2.w, C3.x, C3.y, C3.z, C3.w};
        float dtx = dtv * xv;
        float y = 0.0f;
        if (afast) {
            float e1 = __expf(-dtv);
            float a = 1.0f;
#pragma unroll
            for (int n = 0; n < DSTATE; n++) {
                a *= e1;
                h[n] = h[n] * a + dtx * Bv[n];
                y += h[n] * Cv[n];
            }
        } else {
#pragma unroll
            for (int n = 0; n < DSTATE; n++) {
                float a = __expf(dtv * Aa[n]);
                h[n] = h[n] * a + dtx * Bv[n];
                y += h[n] * Cv[n];
            }
        }
        float zv = g_z[m * DHALF + d];
        g_yz[m * DHALF + d] = (y + Dv * xv) * zv;
    }
}

// ---------------- launch ----------------
extern "C" void kernel_launch(void* const* d_in, const int* in_sizes, int n_in,
                              void* d_out, int out_size)
{
    const float* hidden     = (const float*)d_in[0];
    const float* in_proj_w  = (const float*)d_in[1];
    const float* conv_x_w   = (const float*)d_in[2];
    const float* conv_z_w   = (const float*)d_in[3];
    const float* x_proj_w   = (const float*)d_in[4];
    const float* dt_proj_w  = (const float*)d_in[5];
    const float* dt_proj_b  = (const float*)d_in[6];
    const float* A_log      = (const float*)d_in[7];
    const float* D_param    = (const float*)d_in[8];
    const float* out_proj_w = (const float*)d_in[9];
    const int*   perm_raw   = (const int*)d_in[10];
    float* out = (float*)d_out;

    float *p_xz, *p_x, *p_z, *p_xdbl, *p_dt, *p_yz;
    int   *p_perm;
    cudaGetSymbolAddress((void**)&p_xz,   g_xz);
    cudaGetSymbolAddress((void**)&p_x,    g_x);
    cudaGetSymbolAddress((void**)&p_z,    g_z);
    cudaGetSymbolAddress((void**)&p_xdbl, g_xdbl);
    cudaGetSymbolAddress((void**)&p_dt,   g_dt);
    cudaGetSymbolAddress((void**)&p_yz,   g_yz);
    cudaGetSymbolAddress((void**)&p_perm, g_perm);

    const int mblocks = (MROWS + WBM - 1) / WBM;  // 257

    // 0) canonicalize perm + detect integer-A structure
    prep_kernel<<<1, 1024>>>(perm_raw, A_log);

    // 1) in_proj (tf32 tensor core) with gather-permute
    gemm_wmma<<<dim3(DINNER / WBN, mblocks), 256>>>(
        hidden, in_proj_w, p_xz, MROWS, DINNER, DMODEL,
        DMODEL, DMODEL, DINNER, p_perm, nullptr);

    // 2) depthwise conv + silu
    conv_silu_kernel<<<(MROWS * DHALF + 255) / 256, 256>>>(
        p_xz, conv_x_w, conv_z_w, p_x, p_z);

    // 3) x_proj (SIMT, N=56)
    gemm_nt<0><<<dim3(1, mblocks), 256>>>(
        p_x, x_proj_w, p_xdbl, MROWS, XDBLW, DHALF,
        DHALF, DHALF, XDBLW, nullptr, nullptr, nullptr);

    // 4) dt projection + softplus (SIMT, K=24)
    gemm_nt<1><<<dim3(DHALF / GBN, mblocks), 256>>>(
        p_xdbl, dt_proj_w, p_dt, MROWS, DHALF, DTRANK,
        XDBLW, DTRANK, DHALF, nullptr, nullptr, dt_proj_b);

    // 5) chunked selective scan
    scan_pass1<<<BATCHN * NCH * 3, 128>>>(A_log);
    scan_pass2<<<(BATCHN * DHALF * DSTATE + 255) / 256, 256>>>(A_log);
    scan_pass3<<<BATCHN * NCH * 3, 128>>>(A_log, D_param);

    // 6) out_proj (tf32 tensor core) with scatter
    gemm_wmma<<<dim3(DMODEL / WBN, mblocks), 256>>>(
        p_yz, out_proj_w, out, MROWS, DMODEL, DHALF,
        DHALF, DHALF, DMODEL, nullptr, p_perm);
}

// round 4
// speedup vs baseline: 1.2585x; 1.1070x over previous
#include <cuda_runtime.h>
#include <mma.h>
#include <math.h>

using namespace nvcuda;

// ---------------- problem constants ----------------
#define BATCHN 8
#define SEQLEN 4097
#define LMAIN  4096
#define DMODEL 384
#define DINNER 768
#define DHALF  384
#define DSTATE 16
#define DTRANK 24
#define MROWS  (BATCHN * SEQLEN)        // 32776
#define XDBLW  (DTRANK + 2 * DSTATE)    // 56

#define CHUNK  64
#define NCH    ((SEQLEN + CHUNK - 1) / CHUNK)  // 65

// ---------------- scratch ----------------
__device__ float g_xz   [(size_t)MROWS * DINNER];
__device__ float g_x    [(size_t)MROWS * DHALF];
__device__ float g_z    [(size_t)MROWS * DHALF];
__device__ float g_xdbl [(size_t)MROWS * XDBLW];
__device__ float g_dt   [(size_t)MROWS * DHALF];
__device__ float g_yz   [(size_t)MROWS * DHALF];
__device__ float g_hout [(size_t)BATCHN * NCH * DHALF * DSTATE];
__device__ float g_hin  [(size_t)BATCHN * NCH * DHALF * DSTATE];
__device__ float g_dtsum[(size_t)BATCHN * NCH * DHALF];
__device__ int   g_perm [LMAIN];
__device__ int   g_afast;

// ---------------- prep: perm canonicalization + A-structure detection ----------------
__global__ void __launch_bounds__(1024) prep_kernel(const int* __restrict__ praw,
                                                    const float* __restrict__ A_log)
{
    __shared__ int odd_nonzero;
    __shared__ int a_bad;
    if (threadIdx.x == 0) { odd_nonzero = 0; a_bad = 0; }
    __syncthreads();
    int local = 0;
    for (int i = threadIdx.x; i < LMAIN / 2; i += 1024)
        if (praw[2 * i + 1] != 0) local = 1;
    if (local) atomicOr(&odd_nonzero, 1);

    int bad = 0;
    for (int i = threadIdx.x; i < DHALF * DSTATE; i += 1024) {
        int n = i & 15;
        float ref = logf((float)(n + 1));
        if (fabsf(A_log[i] - ref) > 1e-5f) bad = 1;
    }
    if (bad) atomicOr(&a_bad, 1);
    __syncthreads();
    bool is64 = (odd_nonzero == 0);
    for (int i = threadIdx.x; i < LMAIN; i += 1024)
        g_perm[i] = is64 ? praw[2 * i] : praw[i];
    if (threadIdx.x == 0) g_afast = (a_bad == 0) ? 1 : 0;
}

// ---------------- helpers ----------------
__device__ __forceinline__ int perm_row(int m, const int* __restrict__ p) {
    if (p == nullptr) return m;
    int lp = m % SEQLEN;
    if (lp == 0) return m;
    return m - lp + 1 + p[lp - 1];
}

__device__ __forceinline__ float softplusf(float v) {
    return (v > 20.0f) ? v : log1pf(__expf(v));
}

__device__ __forceinline__ float siluf(float v) {
    return v / (1.0f + __expf(-v));
}

__device__ __forceinline__ float to_tf32(float x) {
    unsigned u;
    asm("cvt.rna.tf32.f32 %0, %1;" : "=r"(u) : "f"(x));
    return __uint_as_float(u);
}

// ---------------- pipelined tf32 GEMM: C[M,N] = A[M,K] * B[N,K]^T ----------------
// BM=128, BN=64, BK=32, 256 threads (8 warps: 4 m x 2 n), warp tile 32x32.
// Register-prefetch double buffering: LDG of tile k+1 overlaps MMA of tile k.
// Row pointers (incl. permutation gather) hoisted out of the k-loop.
#define WBM 128
#define WBN 64
#define WBK 32
#define WLD 36          // BK + 4 padding
#define CLD 68          // BN + 4 padding for epilogue staging

__global__ void __launch_bounds__(256, 2) gemm_tc(
    const float* __restrict__ A, const float* __restrict__ Bw,
    float* __restrict__ C,
    int M, int N, int K, int lda, int ldb, int ldc,
    const int* __restrict__ gperm,
    const int* __restrict__ sperm)
{
    __shared__ float sbuf[WBM * CLD];          // 8704 floats = 34.8KB
    float* As = sbuf;                           // [WBM][WLD] = 4608
    float* Bs = sbuf + WBM * WLD;               // [WBN][WLD] = 2304
    float* Cs = sbuf;                           // epilogue alias [WBM][CLD]

    const int t    = threadIdx.x;
    const int warp = t >> 5;
    const int wm   = warp & 3;
    const int wn   = warp >> 2;
    const int bn0  = blockIdx.x * WBN;
    const int bm0  = blockIdx.y * WBM;

    // hoisted row pointers
    const int ar = t >> 3;          // base row 0..31, +32*i
    const int ac4 = (t & 7) * 4;    // k offset within tile
    const float* aptr[4];
#pragma unroll
    for (int i = 0; i < 4; i++) {
        int m = bm0 + ar + 32 * i;
        if (m >= M) m = M - 1;
        int src = perm_row(m, gperm);
        aptr[i] = A + (size_t)src * lda + ac4;
    }
    const float* bptr[2];
#pragma unroll
    for (int i = 0; i < 2; i++) {
        int n = bn0 + (ar & 63) + ((i == 0) ? 0 : 32);
        // rows: thread covers B rows r and r+32 where r = t>>3 (0..31)
        bptr[i] = Bw + (size_t)n * ldb + ac4;
    }

    wmma::fragment<wmma::accumulator, 16, 16, 8, float> fc[2][2];
#pragma unroll
    for (int i = 0; i < 2; i++)
#pragma unroll
        for (int j = 0; j < 2; j++) wmma::fill_fragment(fc[i][j], 0.0f);

    float4 pa[4], pb[2];

    // prologue: load + store tile 0
#pragma unroll
    for (int i = 0; i < 4; i++) pa[i] = *(const float4*)(aptr[i]);
#pragma unroll
    for (int i = 0; i < 2; i++) pb[i] = *(const float4*)(bptr[i]);
    {
        float* d;
#pragma unroll
        for (int i = 0; i < 4; i++) {
            d = As + (ar + 32 * i) * WLD + ac4;
            d[0] = to_tf32(pa[i].x); d[1] = to_tf32(pa[i].y);
            d[2] = to_tf32(pa[i].z); d[3] = to_tf32(pa[i].w);
        }
#pragma unroll
        for (int i = 0; i < 2; i++) {
            d = Bs + ((ar & 63) + 32 * i) * WLD + ac4;
            d[0] = to_tf32(pb[i].x); d[1] = to_tf32(pb[i].y);
            d[2] = to_tf32(pb[i].z); d[3] = to_tf32(pb[i].w);
        }
    }
    __syncthreads();

    for (int k0 = 0; k0 < K; k0 += WBK) {
        bool more = (k0 + WBK) < K;
        if (more) {
#pragma unroll
            for (int i = 0; i < 4; i++) pa[i] = *(const float4*)(aptr[i] + k0 + WBK);
#pragma unroll
            for (int i = 0; i < 2; i++) pb[i] = *(const float4*)(bptr[i] + k0 + WBK);
        }

#pragma unroll
        for (int ks = 0; ks < WBK; ks += 8) {
            wmma::fragment<wmma::matrix_a, 16, 16, 8, wmma::precision::tf32, wmma::row_major> fa[2];
            wmma::fragment<wmma::matrix_b, 16, 16, 8, wmma::precision::tf32, wmma::col_major> fb[2];
#pragma unroll
            for (int i = 0; i < 2; i++)
                wmma::load_matrix_sync(fa[i], As + (wm * 32 + i * 16) * WLD + ks, WLD);
#pragma unroll
            for (int j = 0; j < 2; j++)
                wmma::load_matrix_sync(fb[j], Bs + (wn * 32 + j * 16) * WLD + ks, WLD);
#pragma unroll
            for (int i = 0; i < 2; i++)
#pragma unroll
                for (int j = 0; j < 2; j++)
                    wmma::mma_sync(fc[i][j], fa[i], fb[j], fc[i][j]);
        }
        __syncthreads();

        if (more) {
            float* d;
#pragma unroll
            for (int i = 0; i < 4; i++) {
                d = As + (ar + 32 * i) * WLD + ac4;
                d[0] = to_tf32(pa[i].x); d[1] = to_tf32(pa[i].y);
                d[2] = to_tf32(pa[i].z); d[3] = to_tf32(pa[i].w);
            }
#pragma unroll
            for (int i = 0; i < 2; i++) {
                d = Bs + ((ar & 63) + 32 * i) * WLD + ac4;
                d[0] = to_tf32(pb[i].x); d[1] = to_tf32(pb[i].y);
                d[2] = to_tf32(pb[i].z); d[3] = to_tf32(pb[i].w);
            }
            __syncthreads();
        }
    }

    // epilogue: stage to smem, permuted coalesced copy out
#pragma unroll
    for (int i = 0; i < 2; i++)
#pragma unroll
        for (int j = 0; j < 2; j++)
            wmma::store_matrix_sync(Cs + (wm * 32 + i * 16) * CLD + wn * 32 + j * 16,
                                    fc[i][j], CLD, wmma::mem_row_major);
    __syncthreads();

#pragma unroll
    for (int i = 0; i < 8; i++) {
        int f  = t + i * 256;
        int r  = f >> 4;
        int c4 = f & 15;
        int m  = bm0 + r;
        if (m >= M) continue;
        int dst = perm_row(m, sperm);
        const float* src = Cs + r * CLD + c4 * 4;
        *(float4*)(C + (size_t)dst * ldc + bn0 + c4 * 4) =
            make_float4(src[0], src[1], src[2], src[3]);
    }
}

// ---------------- 64x64 SIMT GEMM (x_proj): many blocks -> bandwidth-fed ----------------
#define XBK 16
__global__ void __launch_bounds__(256) gemm_nt64(
    const float* __restrict__ A, const float* __restrict__ Bw,
    float* __restrict__ C,
    int M, int N, int K, int lda, int ldb, int ldc)
{
    __shared__ float As[XBK][64];
    __shared__ float Bs[XBK][64];

    const int t   = threadIdx.x;
    const int bm0 = blockIdx.x * 64;
    const int tx  = t & 15;
    const int ty  = t >> 4;

    // hoisted pointers: one A row, one B row per thread
    const int r  = t >> 2;       // 0..63
    const int kq = (t & 3) * 4;  // 0,4,8,12
    int am = bm0 + r; if (am >= M) am = M - 1;
    const float* arow = A + (size_t)am * lda + kq;
    const float* brow = (r < N) ? (Bw + (size_t)r * ldb + kq) : nullptr;

    float acc[4][4];
#pragma unroll
    for (int i = 0; i < 4; i++)
#pragma unroll
        for (int j = 0; j < 4; j++) acc[i][j] = 0.0f;

    for (int k0 = 0; k0 < K; k0 += XBK) {
        float4 va = *(const float4*)(arow + k0);
        float4 vb = brow ? *(const float4*)(brow + k0) : make_float4(0.f, 0.f, 0.f, 0.f);
        As[kq + 0][r] = va.x; As[kq + 1][r] = va.y;
        As[kq + 2][r] = va.z; As[kq + 3][r] = va.w;
        Bs[kq + 0][r] = vb.x; Bs[kq + 1][r] = vb.y;
        Bs[kq + 2][r] = vb.z; Bs[kq + 3][r] = vb.w;
        __syncthreads();

#pragma unroll
        for (int kk = 0; kk < XBK; kk++) {
            float4 a0 = *(const float4*)&As[kk][ty * 4];
            float4 b0 = *(const float4*)&Bs[kk][tx * 4];
            float av[4] = {a0.x, a0.y, a0.z, a0.w};
            float bv[4] = {b0.x, b0.y, b0.z, b0.w};
#pragma unroll
            for (int i = 0; i < 4; i++)
#pragma unroll
                for (int j = 0; j < 4; j++) acc[i][j] += av[i] * bv[j];
        }
        __syncthreads();
    }

#pragma unroll
    for (int i = 0; i < 4; i++) {
        int m = bm0 + ty * 4 + i;
        if (m >= M) continue;
#pragma unroll
        for (int j = 0; j < 4; j++) {
            int n = tx * 4 + j;
            if (n >= N) continue;
            C[(size_t)m * ldc + n] = acc[i][j];
        }
    }
}

// ---------------- SIMT NT GEMM (dt projection) ----------------
#define GBM 128
#define GBN 64
#define GBK 16

template <int EPI>
__global__ void __launch_bounds__(256) gemm_nt(
    const float* __restrict__ A, const float* __restrict__ Bw,
    float* __restrict__ C,
    int M, int N, int K, int lda, int ldb, int ldc,
    const int* __restrict__ gperm,
    const int* __restrict__ sperm,
    const float* __restrict__ bias)
{
    __shared__ float As[GBK][GBM];
    __shared__ float Bs[GBK][GBN];

    const int t   = threadIdx.x;
    const int bn0 = blockIdx.x * GBN;
    const int bm0 = blockIdx.y * GBM;
    const int tx  = t & 15;
    const int ty  = t >> 4;

    float acc[8][4];
#pragma unroll
    for (int i = 0; i < 8; i++)
#pragma unroll
        for (int j = 0; j < 4; j++) acc[i][j] = 0.0f;

    for (int k0 = 0; k0 < K; k0 += GBK) {
#pragma unroll
        for (int i = 0; i < 2; i++) {
            int id = t + i * 256;
            int r  = id >> 2;
            int kq = id & 3;
            int m  = bm0 + r;
            float4 v = make_float4(0.f, 0.f, 0.f, 0.f);
            if (m < M && (k0 + kq * 4) < K) {
                int src = perm_row(m, gperm);
                v = *(const float4*)(A + (size_t)src * lda + k0 + kq * 4);
            }
            As[kq * 4 + 0][r] = v.x;
            As[kq * 4 + 1][r] = v.y;
            As[kq * 4 + 2][r] = v.z;
            As[kq * 4 + 3][r] = v.w;
        }
        {
            int r  = t >> 2;
            int kq = t & 3;
            int n  = bn0 + r;
            float4 v = make_float4(0.f, 0.f, 0.f, 0.f);
            if (n < N && (k0 + kq * 4) < K)
                v = *(const float4*)(Bw + (size_t)n * ldb + k0 + kq * 4);
            Bs[kq * 4 + 0][r] = v.x;
            Bs[kq * 4 + 1][r] = v.y;
            Bs[kq * 4 + 2][r] = v.z;
            Bs[kq * 4 + 3][r] = v.w;
        }
        __syncthreads();

#pragma unroll
        for (int kk = 0; kk < GBK; kk++) {
            float4 a0 = *(const float4*)&As[kk][ty * 8];
            float4 a1 = *(const float4*)&As[kk][ty * 8 + 4];
            float4 b0 = *(const float4*)&Bs[kk][tx * 4];
            float av[8] = {a0.x, a0.y, a0.z, a0.w, a1.x, a1.y, a1.z, a1.w};
            float bv[4] = {b0.x, b0.y, b0.z, b0.w};
#pragma unroll
            for (int i = 0; i < 8; i++)
#pragma unroll
                for (int j = 0; j < 4; j++) acc[i][j] += av[i] * bv[j];
        }
        __syncthreads();
    }

#pragma unroll
    for (int i = 0; i < 8; i++) {
        int m = bm0 + ty * 8 + i;
        if (m >= M) continue;
        int dst = perm_row(m, sperm);
#pragma unroll
        for (int j = 0; j < 4; j++) {
            int n = bn0 + tx * 4 + j;
            if (n >= N) continue;
            float v = acc[i][j];
            if (EPI == 1) v = softplusf(v + bias[n]);
            C[(size_t)dst * ldc + n] = v;
        }
    }
}

// ---------------- depthwise conv (k=4, pad 1/2) + SiLU, float4 over channels ----------------
__global__ void conv_silu_kernel(const float* __restrict__ xz,
                                 const float* __restrict__ wx,
                                 const float* __restrict__ wz,
                                 float* __restrict__ xo,
                                 float* __restrict__ zo)
{
    int idx = blockIdx.x * blockDim.x + threadIdx.x;
    const int NC4 = DHALF / 4;   // 96
    if (idx >= MROWS * NC4) return;
    int c4 = idx % NC4;
    int m  = idx / NC4;
    int l  = m % SEQLEN;
    int b  = m / SEQLEN;

    float ax[4] = {0.f, 0.f, 0.f, 0.f};
    float az[4] = {0.f, 0.f, 0.f, 0.f};
#pragma unroll
    for (int k = 0; k < 4; k++) {
        int ll = l - 1 + k;
        if (ll < 0 || ll >= SEQLEN) continue;
        const float* p = xz + ((size_t)(b * SEQLEN + ll)) * DINNER;
        float4 vx = *(const float4*)(p + c4 * 4);
        float4 vz = *(const float4*)(p + DHALF + c4 * 4);
        float vxa[4] = {vx.x, vx.y, vx.z, vx.w};
        float vza[4] = {vz.x, vz.y, vz.z, vz.w};
#pragma unroll
        for (int j = 0; j < 4; j++) {
            int cc = c4 * 4 + j;
            ax[j] += wx[cc * 4 + k] * vxa[j];
            az[j] += wz[cc * 4 + k] * vza[j];
        }
    }
    float4 ox = make_float4(siluf(ax[0]), siluf(ax[1]), siluf(ax[2]), siluf(ax[3]));
    float4 oz = make_float4(siluf(az[0]), siluf(az[1]), siluf(az[2]), siluf(az[3]));
    *(float4*)(xo + (size_t)m * DHALF + c4 * 4) = ox;
    *(float4*)(zo + (size_t)m * DHALF + c4 * 4) = oz;
}

// ---------------- scan pass 1 ----------------
__global__ void __launch_bounds__(128) scan_pass1(const float* __restrict__ A_log)
{
    int bid = blockIdx.x;
    int dg  = bid % 3;
    int c   = (bid / 3) % NCH;
    int b   = bid / (3 * NCH);
    int d   = dg * 128 + threadIdx.x;
    const bool afast = (g_afast != 0);

    float Aa[DSTATE];
#pragma unroll
    for (int n = 0; n < DSTATE; n++) Aa[n] = -__expf(A_log[d * DSTATE + n]);

    float h[DSTATE];
#pragma unroll
    for (int n = 0; n < DSTATE; n++) h[n] = 0.0f;
    float dts = 0.0f;

    int t0 = c * CHUNK;
    int t1 = min(SEQLEN, t0 + CHUNK);
    for (int t = t0; t < t1; t++) {
        size_t m  = (size_t)b * SEQLEN + t;
        float dtv = g_dt[m * DHALF + d];
        float xv  = g_x[m * DHALF + d];
        dts += dtv;
        const float4* Bp = (const float4*)(g_xdbl + m * XDBLW + DTRANK);
        float4 B0 = Bp[0], B1 = Bp[1], B2 = Bp[2], B3 = Bp[3];
        float Bv[DSTATE] = {B0.x, B0.y, B0.z, B0.w, B1.x, B1.y, B1.z, B1.w,
                            B2.x, B2.y, B2.z, B2.w, B3.x, B3.y, B3.z, B3.w};
        float dtx = dtv * xv;
        if (afast) {
            float e1 = __expf(-dtv);
            float a = 1.0f;
#pragma unroll
            for (int n = 0; n < DSTATE; n++) {
                a *= e1;
                h[n] = h[n] * a + dtx * Bv[n];
            }
        } else {
#pragma unroll
            for (int n = 0; n < DSTATE; n++) {
                float a = __expf(dtv * Aa[n]);
                h[n] = h[n] * a + dtx * Bv[n];
            }
        }
    }

    size_t base = ((size_t)b * NCH + c) * DHALF + d;
    float4* ho = (float4*)(g_hout + base * DSTATE);
    ho[0] = make_float4(h[0], h[1], h[2], h[3]);
    ho[1] = make_float4(h[4], h[5], h[6], h[7]);
    ho[2] = make_float4(h[8], h[9], h[10], h[11]);
    ho[3] = make_float4(h[12], h[13], h[14], h[15]);
    g_dtsum[base] = dts;
}

// ---------------- scan pass 2 ----------------
__global__ void scan_pass2(const float* __restrict__ A_log)
{
    int idx = blockIdx.x * blockDim.x + threadIdx.x;
    if (idx >= BATCHN * DHALF * DSTATE) return;
    int n = idx & 15;
    int d = (idx >> 4) % DHALF;
    int b = idx / (DSTATE * DHALF);

    float Aa = -__expf(A_log[d * DSTATE + n]);
    float h = 0.0f;
    for (int c = 0; c < NCH; c++) {
        size_t base = ((size_t)b * NCH + c) * DHALF + d;
        g_hin[base * DSTATE + n] = h;
        float a = __expf(Aa * g_dtsum[base]);
        h = h * a + g_hout[base * DSTATE + n];
    }
}

// ---------------- scan pass 3 ----------------
__global__ void __launch_bounds__(128) scan_pass3(const float* __restrict__ A_log,
                                                  const float* __restrict__ D_param)
{
    int bid = blockIdx.x;
    int dg  = bid % 3;
    int c   = (bid / 3) % NCH;
    int b   = bid / (3 * NCH);
    int d   = dg * 128 + threadIdx.x;
    const bool afast = (g_afast != 0);

    float Aa[DSTATE];
#pragma unroll
    for (int n = 0; n < DSTATE; n++) Aa[n] = -__expf(A_log[d * DSTATE + n]);
    float Dv = D_param[d];

    size_t sbase = ((size_t)b * NCH + c) * DHALF + d;
    const float4* hi = (const float4*)(g_hin + sbase * DSTATE);
    float4 h0 = hi[0], h1 = hi[1], h2 = hi[2], h3 = hi[3];
    float h[DSTATE] = {h0.x, h0.y, h0.z, h0.w, h1.x, h1.y, h1.z, h1.w,
                       h2.x, h2.y, h2.z, h2.w, h3.x, h3.y, h3.z, h3.w};

    int t0 = c * CHUNK;
    int t1 = min(SEQLEN, t0 + CHUNK);
    for (int t = t0; t < t1; t++) {
        size_t m  = (size_t)b * SEQLEN + t;
        float dtv = g_dt[m * DHALF + d];
        float xv  = g_x[m * DHALF + d];
        const float4* Bp = (const float4*)(g_xdbl + m * XDBLW + DTRANK);
        float4 B0 = Bp[0], B1 = Bp[1], B2 = Bp[2], B3 = Bp[3];
        const float4* Cp = (const float4*)(g_xdbl + m * XDBLW + DTRANK + DSTATE);
        float4 C0 = Cp[0], C1 = Cp[1], C2 = Cp[2], C3 = Cp[3];
        float Bv[DSTATE] = {B0.x, B0.y, B0.z, B0.w, B1.x, B1.y, B1.z, B1.w,
                            B2.x, B2.y, B2.z, B2.w, B3.x, B3.y, B3.z, B3.w};
        float Cv[DSTATE] = {C0.x, C0.y, C0.z, C0.w, C1.x, C1.y, C1.z, C1.w,
                            C2.x, C2.y, C2.z, C2.w, C3.x, C3.y, C3.z, C3.w};
        float dtx = dtv * xv;
        float y = 0.0f;
        if (afast) {
            float e1 = __expf(-dtv);
            float a = 1.0f;
#pragma unroll
            for (int n = 0; n < DSTATE; n++) {
                a *= e1;
                h[n] = h[n] * a + dtx * Bv[n];
                y += h[n] * Cv[n];
            }
        } else {
#pragma unroll
            for (int n = 0; n < DSTATE; n++) {
                float a = __expf(dtv * Aa[n]);
                h[n] = h[n] * a + dtx * Bv[n];
                y += h[n] * Cv[n];
            }
        }
        float zv = g_z[m * DHALF + d];
        g_yz[m * DHALF + d] = (y + Dv * xv) * zv;
    }
}

// ---------------- launch ----------------
extern "C" void kernel_launch(void* const* d_in, const int* in_sizes, int n_in,
                              void* d_out, int out_size)
{
    const float* hidden     = (const float*)d_in[0];
    const float* in_proj_w  = (const float*)d_in[1];
    const float* conv_x_w   = (const float*)d_in[2];
    const float* conv_z_w   = (const float*)d_in[3];
    const float* x_proj_w   = (const float*)d_in[4];
    const float* dt_proj_w  = (const float*)d_in[5];
    const float* dt_proj_b  = (const float*)d_in[6];
    const float* A_log      = (const float*)d_in[7];
    const float* D_param    = (const float*)d_in[8];
    const float* out_proj_w = (const float*)d_in[9];
    const int*   perm_raw   = (const int*)d_in[10];
    float* out = (float*)d_out;

    float *p_xz, *p_x, *p_z, *p_xdbl, *p_dt, *p_yz;
    int   *p_perm;
    cudaGetSymbolAddress((void**)&p_xz,   g_xz);
    cudaGetSymbolAddress((void**)&p_x,    g_x);
    cudaGetSymbolAddress((void**)&p_z,    g_z);
    cudaGetSymbolAddress((void**)&p_xdbl, g_xdbl);
    cudaGetSymbolAddress((void**)&p_dt,   g_dt);
    cudaGetSymbolAddress((void**)&p_yz,   g_yz);
    cudaGetSymbolAddress((void**)&p_perm, g_perm);

    const int mblocks = (MROWS + WBM - 1) / WBM;  // 257

    prep_kernel<<<1, 1024>>>(perm_raw, A_log);

    // 1) in_proj (pipelined tf32) with gather-permute
    gemm_tc<<<dim3(DINNER / WBN, mblocks), 256>>>(
        hidden, in_proj_w, p_xz, MROWS, DINNER, DMODEL,
        DMODEL, DMODEL, DINNER, p_perm, nullptr);

    // 2) depthwise conv + silu (float4)
    conv_silu_kernel<<<(MROWS * (DHALF / 4) + 255) / 256, 256>>>(
        p_xz, conv_x_w, conv_z_w, p_x, p_z);

    // 3) x_proj (64x64 SIMT, 513 blocks)
    gemm_nt64<<<(MROWS + 63) / 64, 256>>>(
        p_x, x_proj_w, p_xdbl, MROWS, XDBLW, DHALF,
        DHALF, DHALF, XDBLW);

    // 4) dt projection + softplus
    gemm_nt<1><<<dim3(DHALF / GBN, mblocks), 256>>>(
        p_xdbl, dt_proj_w, p_dt, MROWS, DHALF, DTRANK,
        XDBLW, DTRANK, DHALF, nullptr, nullptr, dt_proj_b);

    // 5) chunked selective scan
    scan_pass1<<<BATCHN * NCH * 3, 128>>>(A_log);
    scan_pass2<<<(BATCHN * DHALF * DSTATE + 255) / 256, 256>>>(A_log);
    scan_pass3<<<BATCHN * NCH * 3, 128>>>(A_log, D_param);

    // 6) out_proj (pipelined tf32) with scatter
    gemm_tc<<<dim3(DMODEL / WBN, mblocks), 256>>>(
        p_yz, out_proj_w, out, MROWS, DMODEL, DHALF,
        DHALF, DHALF, DMODEL, nullptr, p_perm);
}